// round 16
// baseline (speedup 1.0000x reference)
#include <cuda_runtime.h>
#include <cuda_fp16.h>
#include <cstdint>

// QuadraticConv2D implicit GEMM on fp16 mma.sync (f32 accumulate).
// out[m,o] = sum_{l,c} F_l[m,c] * W[l,c,o];  M=65536, K=54*64 (+exact bias), N=64.
// CTA: 256 thr, 256 m rows (4 image rows), warp tile m32n64, grid 256.
// x staged fp16 in smem (57KB, conflict-free stride-72).
// W fragment-packed in gmem; B fragments via coalesced LDG.128.
// B fragments PING-PONG-PREFETCHED one q-step ahead (incl. across feature
// boundaries) -> L2 latency (warp-drift L1 misses) fully hidden under MMAs.
// A fragments built just-in-time (29-cyc LDS, absorbed by warp multiplexing).

#define XS_STRIDE 72                    // halfs per w position (conflict-free)
#define XS_ROW    (66 * XS_STRIDE)      // 4752 halfs per image row
#define XS_HALFS  (6 * XS_ROW)          // 28512
#define SMEM_BYTES (XS_HALFS * 2)       // 57024 B

// Fragment-packed weights: Wf[l][q][g2][lane] -> uint4 =
//   { b0(nt=2g2), b1(2g2), b0(2g2+1), b1(2g2+1) } for that lane.
__device__ __align__(16) uint4 Wfg[54 * 16 * 32];
__device__ float bvecg[64];             // exact bias contribution (fp32)

__constant__ unsigned char F_I[54] = {
    0,0,0,0,0,0,0,0,0,0, 1,1,1,1,1,1,1,1,1, 2,2,2,2,2,2,2,2,
    3,3,3,3,3,3,3, 4,4,4,4,4,4, 5,5,5,5,5, 6,6,6,6, 7,7,7, 8,8};
__constant__ unsigned char F_J[54] = {
    0,1,2,3,4,5,6,7,8,255, 1,2,3,4,5,6,7,8,255, 2,3,4,5,6,7,8,255,
    3,4,5,6,7,8,255, 4,5,6,7,8,255, 5,6,7,8,255, 6,7,8,255, 7,8,255, 8,255};
__constant__ unsigned char F_L[54] = {
    0,1,2,3,4,5,6,7,8,45, 9,10,11,12,13,14,15,16,46, 17,18,19,20,21,22,23,47,
    24,25,26,27,28,29,48, 30,31,32,33,34,49, 35,36,37,38,50,
    39,40,41,51, 42,43,52, 44,53};

static __device__ __forceinline__ void mma16816(float* d,
    uint32_t a0, uint32_t a1, uint32_t a2, uint32_t a3,
    uint32_t b0, uint32_t b1) {
    asm volatile(
        "mma.sync.aligned.m16n8k16.row.col.f32.f16.f16.f32 "
        "{%0,%1,%2,%3}, {%4,%5,%6,%7}, {%8,%9}, {%0,%1,%2,%3};"
        : "+f"(d[0]), "+f"(d[1]), "+f"(d[2]), "+f"(d[3])
        : "r"(a0), "r"(a1), "r"(a2), "r"(a3), "r"(b0), "r"(b1));
}
static __device__ __forceinline__ uint32_t lds32(uint32_t addr) {
    uint32_t v;
    asm volatile("ld.shared.b32 %0, [%1];" : "=r"(v) : "r"(addr));
    return v;
}
static __device__ __forceinline__ uint32_t packh2(float a, float b) {
    const __half2 h = __floats2half2_rn(a, b);
    return *(const uint32_t*)&h;
}

// ---- prep: fragment-pack W into Wfg; exact fp32 bias column sums ----
__global__ void prep_W(const float* __restrict__ wk) {
    const int l = blockIdx.x;
    if (l < 54) {
        const int tid = threadIdx.x;          // 512 threads = 16 frag-groups x 32
        const int q    = tid >> 7;
        const int g2   = (tid >> 5) & 3;
        const int lane = tid & 31;
        const int r = lane >> 2, t4 = lane & 3;
        const int n0 = (2 * g2) * 8 + r;
        const int n1 = (2 * g2 + 1) * 8 + r;
        const int k0 = 16 * q + 2 * t4;
        const float* w = wk + l * 4096;
        uint4 v;
        v.x = packh2(w[(k0    ) * 64 + n0], w[(k0 + 1) * 64 + n0]);
        v.y = packh2(w[(k0 + 8) * 64 + n0], w[(k0 + 9) * 64 + n0]);
        v.z = packh2(w[(k0    ) * 64 + n1], w[(k0 + 1) * 64 + n1]);
        v.w = packh2(w[(k0 + 8) * 64 + n1], w[(k0 + 9) * 64 + n1]);
        Wfg[(l * 16 + q * 4 + g2) * 32 + lane] = v;
    } else if (threadIdx.x < 64) {
        float s = 0.f;
        for (int c = 0; c < 64; ++c) s += wk[54 * 4096 + c * 64 + threadIdx.x];
        bvecg[threadIdx.x] = s;
    }
}

// build the 4 A-fragments (one q-step) from tap addresses
static __device__ __forceinline__ void build_ha(uint32_t (*dst)[2],
                                                const uint32_t* ib,
                                                const uint32_t* jb,
                                                int q, bool quad) {
    #pragma unroll
    for (int mi = 0; mi < 4; ++mi) {
        uint32_t v0 = lds32(ib[mi] + q * 32);
        uint32_t v1 = lds32(ib[mi] + q * 32 + 16);
        if (quad) {
            const uint32_t w0 = lds32(jb[mi] + q * 32);
            const uint32_t w1 = lds32(jb[mi] + q * 32 + 16);
            const __half2 p0 = __hmul2(*(const __half2*)&v0,
                                       *(const __half2*)&w0);
            const __half2 p1 = __hmul2(*(const __half2*)&v1,
                                       *(const __half2*)&w1);
            v0 = *(const uint32_t*)&p0;
            v1 = *(const uint32_t*)&p1;
        }
        dst[mi][0] = v0;
        dst[mi][1] = v1;
    }
}

// --------------------------------- main -------------------------------------
__global__ __launch_bounds__(256, 2)
void qconv_mma(const float* __restrict__ x, float* __restrict__ out) {
    extern __shared__ __half xsm[];
    __half* xs = xsm;
    const uint32_t sb = (uint32_t)__cvta_generic_to_shared(xsm);

    const int t    = threadIdx.x;
    const int warp = t >> 5, lane = t & 31;
    const int r    = lane >> 2, t4 = lane & 3;
    const int irow  = warp >> 1;          // image row within CTA (0..3)
    const int wbase = (warp & 1) * 32;    // w offset within image row
    const int bb = blockIdx.x >> 4;
    const int r0 = (blockIdx.x & 15) * 4;

    // ---- stage 6 x-rows as fp16 (stride-72, zero halo) ----
    #pragma unroll
    for (int rr = 0; rr < 6; ++rr) {
        const int hh = r0 + rr - 1;
        const bool ok = (hh >= 0 && hh < 64);
        const float4* src =
            (const float4*)(x + (size_t)(bb * 64 + (ok ? hh : 0)) * 4096);
        #pragma unroll
        for (int k = 0; k < 4; ++k) {
            const int idx = t + k * 256;          // float4 idx 0..1023
            const int ww = idx >> 4, c4 = idx & 15;
            const float4 v = ok ? src[idx] : make_float4(0.f, 0.f, 0.f, 0.f);
            uint2 pk;
            pk.x = packh2(v.x, v.y);
            pk.y = packh2(v.z, v.w);
            *(uint2*)(xs + rr * XS_ROW + (ww + 1) * XS_STRIDE + c4 * 4) = pk;
        }
    }
    if (t < 192) {
        const int rr = t >> 5, side = (t >> 4) & 1, c4 = t & 15;
        *(uint2*)(xs + rr * XS_ROW + (side ? 65 : 0) * XS_STRIDE + c4 * 4) =
            make_uint2(0u, 0u);
    }
    __syncthreads();          // the ONLY barrier

    float acc[2][8][4];
    #pragma unroll
    for (int a = 0; a < 2; ++a)
        #pragma unroll
        for (int b = 0; b < 8; ++b)
            #pragma unroll
            for (int cc = 0; cc < 4; ++cc) acc[a][b][cc] = 0.f;

    // ---- B-fragment ping-pong prefetch: warm q=0 of feature 0 ----
    const uint4* wf = Wfg + (size_t)(F_L[0] * 16) * 32 + lane;
    uint4 bv[2][4];
    #pragma unroll
    for (int g2 = 0; g2 < 4; ++g2) bv[0][g2] = __ldg(wf + g2 * 32);

    uint32_t ib[4], jb[4];
    uint32_t ha[4][2];

    for (int f = 0; f < 54; ++f) {
        const uint4* wfn =
            Wfg + (size_t)(F_L[(f + 1 < 54) ? f + 1 : f] * 16) * 32 + lane;

        // tap addresses for this feature (ALU only, hidden)
        const int ii = F_I[f], jj = F_J[f];
        const int di = ii / 3, dj = ii % 3;
        const bool quad = (jj != 255);
        const int dr = quad ? jj / 3 : di, dc = quad ? jj % 3 : dj;
        #pragma unroll
        for (int mi = 0; mi < 4; ++mi) {
            const int wp = wbase + mi * 8 + r;
            ib[mi] = sb + ((irow + di) * XS_ROW + (wp + dj) * XS_STRIDE) * 2
                   + t4 * 4;
            jb[mi] = sb + ((irow + dr) * XS_ROW + (wp + dc) * XS_STRIDE) * 2
                   + t4 * 4;
        }

        #pragma unroll
        for (int q = 0; q < 4; ++q) {
            // prefetch NEXT q-step's B fragments (or next feature's q=0)
            const uint4* wsrc = (q < 3) ? (wf + (q + 1) * 4 * 32) : wfn;
            #pragma unroll
            for (int g2 = 0; g2 < 4; ++g2)
                bv[(q + 1) & 1][g2] = __ldg(wsrc + g2 * 32);

            // A fragments for this q (short LDS chain, warp-multiplexed)
            build_ha(ha, ib, jb, q, quad);

            const uint4* bc = bv[q & 1];
            #pragma unroll
            for (int g2 = 0; g2 < 4; ++g2) {
                mma16816(acc[0][2 * g2],     ha[0][0], ha[1][0], ha[0][1],
                         ha[1][1], bc[g2].x, bc[g2].y);
                mma16816(acc[0][2 * g2 + 1], ha[0][0], ha[1][0], ha[0][1],
                         ha[1][1], bc[g2].z, bc[g2].w);
                mma16816(acc[1][2 * g2],     ha[2][0], ha[3][0], ha[2][1],
                         ha[3][1], bc[g2].x, bc[g2].y);
                mma16816(acc[1][2 * g2 + 1], ha[2][0], ha[3][0], ha[2][1],
                         ha[3][1], bc[g2].z, bc[g2].w);
            }
        }
        wf = wfn;
    }

    // ---- epilogue: exact bias add + float2 stores ----
    const int mrow0 = blockIdx.x * 256 + warp * 32 + r;
    #pragma unroll
    for (int mb = 0; mb < 2; ++mb) {
        #pragma unroll
        for (int nt = 0; nt < 8; ++nt) {
            const int n = nt * 8 + t4 * 2;
            const float bvx = bvecg[n], bvy = bvecg[n + 1];
            float* o0 = out + (size_t)(mrow0 + mb * 16) * 64 + n;
            *(float2*)o0 = make_float2(acc[mb][nt][0] + bvx, acc[mb][nt][1] + bvy);
            *(float2*)(o0 + 8 * 64) =
                make_float2(acc[mb][nt][2] + bvx, acc[mb][nt][3] + bvy);
        }
    }
}

extern "C" void kernel_launch(void* const* d_in, const int* in_sizes, int n_in,
                              void* d_out, int out_size) {
    const float* x  = (const float*)d_in[0];
    const float* wk = (const float*)d_in[1];   // [55,64,64] (l,c,o) contiguous
    float* out = (float*)d_out;

    prep_W<<<55, 512>>>(wk);
    cudaFuncSetAttribute(qconv_mma,
                         cudaFuncAttributeMaxDynamicSharedMemorySize, SMEM_BYTES);
    qconv_mma<<<256, 256, SMEM_BYTES>>>(x, out);
}

// round 17
// speedup vs baseline: 1.0003x; 1.0003x over previous
#include <cuda_runtime.h>
#include <cuda_fp16.h>
#include <cstdint>

// QuadraticConv2D implicit GEMM on fp16 mma.sync (f32 accumulate).
// out[m,o] = sum_{l,c} F_l[m,c] * W[l,c,o];  M=65536, K=54*64 (+exact bias), N=64.
// CTA: 128 thr (4 warps), 256 m rows; WARP TILE m64n64 (one full image row).
// Doubling warp-M amortizes B fragments over 2x MACs -> 0.0915 B/MAC, pushing
// the L1 wavefront load (~78k cyc/SM) under the tensor floor (~110k cyc).
// x staged fp16 in smem (57KB, conflict-free stride-72); W fragment-packed in
// gmem, B ping-pong-prefetched one q-step ahead. 256 regs/thread, 2 CTAs/SM.

#define XS_STRIDE 72                    // halfs per w position (conflict-free)
#define XS_ROW    (66 * XS_STRIDE)      // 4752 halfs per image row
#define XS_HALFS  (6 * XS_ROW)          // 28512
#define SMEM_BYTES (XS_HALFS * 2)       // 57024 B

// Fragment-packed weights: Wf[l][q][g2][lane] -> uint4 =
//   { b0(nt=2g2), b1(2g2), b0(2g2+1), b1(2g2+1) } for that lane.
__device__ __align__(16) uint4 Wfg[54 * 16 * 32];
__device__ float bvecg[64];             // exact bias contribution (fp32)

__constant__ unsigned char F_I[54] = {
    0,0,0,0,0,0,0,0,0,0, 1,1,1,1,1,1,1,1,1, 2,2,2,2,2,2,2,2,
    3,3,3,3,3,3,3, 4,4,4,4,4,4, 5,5,5,5,5, 6,6,6,6, 7,7,7, 8,8};
__constant__ unsigned char F_J[54] = {
    0,1,2,3,4,5,6,7,8,255, 1,2,3,4,5,6,7,8,255, 2,3,4,5,6,7,8,255,
    3,4,5,6,7,8,255, 4,5,6,7,8,255, 5,6,7,8,255, 6,7,8,255, 7,8,255, 8,255};
__constant__ unsigned char F_L[54] = {
    0,1,2,3,4,5,6,7,8,45, 9,10,11,12,13,14,15,16,46, 17,18,19,20,21,22,23,47,
    24,25,26,27,28,29,48, 30,31,32,33,34,49, 35,36,37,38,50,
    39,40,41,51, 42,43,52, 44,53};

static __device__ __forceinline__ void mma16816(float* d,
    uint32_t a0, uint32_t a1, uint32_t a2, uint32_t a3,
    uint32_t b0, uint32_t b1) {
    asm volatile(
        "mma.sync.aligned.m16n8k16.row.col.f32.f16.f16.f32 "
        "{%0,%1,%2,%3}, {%4,%5,%6,%7}, {%8,%9}, {%0,%1,%2,%3};"
        : "+f"(d[0]), "+f"(d[1]), "+f"(d[2]), "+f"(d[3])
        : "r"(a0), "r"(a1), "r"(a2), "r"(a3), "r"(b0), "r"(b1));
}
static __device__ __forceinline__ uint32_t lds32(uint32_t addr) {
    uint32_t v;
    asm volatile("ld.shared.b32 %0, [%1];" : "=r"(v) : "r"(addr));
    return v;
}
static __device__ __forceinline__ uint32_t packh2(float a, float b) {
    const __half2 h = __floats2half2_rn(a, b);
    return *(const uint32_t*)&h;
}

// ---- prep: fragment-pack W into Wfg; exact fp32 bias column sums ----
__global__ void prep_W(const float* __restrict__ wk) {
    const int l = blockIdx.x;
    if (l < 54) {
        const int tid = threadIdx.x;          // 512 threads = 16 frag-groups x 32
        const int q    = tid >> 7;
        const int g2   = (tid >> 5) & 3;
        const int lane = tid & 31;
        const int r = lane >> 2, t4 = lane & 3;
        const int n0 = (2 * g2) * 8 + r;
        const int n1 = (2 * g2 + 1) * 8 + r;
        const int k0 = 16 * q + 2 * t4;
        const float* w = wk + l * 4096;
        uint4 v;
        v.x = packh2(w[(k0    ) * 64 + n0], w[(k0 + 1) * 64 + n0]);
        v.y = packh2(w[(k0 + 8) * 64 + n0], w[(k0 + 9) * 64 + n0]);
        v.z = packh2(w[(k0    ) * 64 + n1], w[(k0 + 1) * 64 + n1]);
        v.w = packh2(w[(k0 + 8) * 64 + n1], w[(k0 + 9) * 64 + n1]);
        Wfg[(l * 16 + q * 4 + g2) * 32 + lane] = v;
    } else if (threadIdx.x < 64) {
        float s = 0.f;
        for (int c = 0; c < 64; ++c) s += wk[54 * 4096 + c * 64 + threadIdx.x];
        bvecg[threadIdx.x] = s;
    }
}

// build the 8 A-fragment pairs (one q-step, m64) from tap addresses
static __device__ __forceinline__ void build_ha(uint32_t (*dst)[2],
                                                const uint32_t* ib,
                                                const uint32_t* jb,
                                                int q, bool quad) {
    #pragma unroll
    for (int mi = 0; mi < 8; ++mi) {
        uint32_t v0 = lds32(ib[mi] + q * 32);
        uint32_t v1 = lds32(ib[mi] + q * 32 + 16);
        if (quad) {
            const uint32_t w0 = lds32(jb[mi] + q * 32);
            const uint32_t w1 = lds32(jb[mi] + q * 32 + 16);
            const __half2 p0 = __hmul2(*(const __half2*)&v0,
                                       *(const __half2*)&w0);
            const __half2 p1 = __hmul2(*(const __half2*)&v1,
                                       *(const __half2*)&w1);
            v0 = *(const uint32_t*)&p0;
            v1 = *(const uint32_t*)&p1;
        }
        dst[mi][0] = v0;
        dst[mi][1] = v1;
    }
}

// --------------------------------- main -------------------------------------
__global__ __launch_bounds__(128, 2)
void qconv_mma(const float* __restrict__ x, float* __restrict__ out) {
    extern __shared__ __half xsm[];
    __half* xs = xsm;
    const uint32_t sb = (uint32_t)__cvta_generic_to_shared(xsm);

    const int t    = threadIdx.x;
    const int warp = t >> 5, lane = t & 31;
    const int r    = lane >> 2, t4 = lane & 3;
    const int irow = warp;                // warp = one full image row (m64)
    const int bb = blockIdx.x >> 4;
    const int r0 = (blockIdx.x & 15) * 4;

    // ---- stage 6 x-rows as fp16 (stride-72, zero halo), 128 threads ----
    #pragma unroll
    for (int rr = 0; rr < 6; ++rr) {
        const int hh = r0 + rr - 1;
        const bool ok = (hh >= 0 && hh < 64);
        const float4* src =
            (const float4*)(x + (size_t)(bb * 64 + (ok ? hh : 0)) * 4096);
        #pragma unroll
        for (int k = 0; k < 8; ++k) {
            const int idx = t + k * 128;          // float4 idx 0..1023
            const int ww = idx >> 4, c4 = idx & 15;
            const float4 v = ok ? src[idx] : make_float4(0.f, 0.f, 0.f, 0.f);
            uint2 pk;
            pk.x = packh2(v.x, v.y);
            pk.y = packh2(v.z, v.w);
            *(uint2*)(xs + rr * XS_ROW + (ww + 1) * XS_STRIDE + c4 * 4) = pk;
        }
    }
    for (int s = t; s < 192; s += 128) {
        const int rr = s >> 5, side = (s >> 4) & 1, c4 = s & 15;
        *(uint2*)(xs + rr * XS_ROW + (side ? 65 : 0) * XS_STRIDE + c4 * 4) =
            make_uint2(0u, 0u);
    }
    __syncthreads();          // the ONLY barrier

    float acc[4][8][4];       // [m16 blk 0..3][n8 blk][4]
    #pragma unroll
    for (int a = 0; a < 4; ++a)
        #pragma unroll
        for (int b = 0; b < 8; ++b)
            #pragma unroll
            for (int cc = 0; cc < 4; ++cc) acc[a][b][cc] = 0.f;

    // ---- B-fragment ping-pong prefetch: warm q=0 of feature 0 ----
    const uint4* wf = Wfg + (size_t)(F_L[0] * 16) * 32 + lane;
    uint4 bv[2][4];
    #pragma unroll
    for (int g2 = 0; g2 < 4; ++g2) bv[0][g2] = __ldg(wf + g2 * 32);

    uint32_t ib[8], jb[8];
    uint32_t ha[8][2];

    for (int f = 0; f < 54; ++f) {
        const uint4* wfn =
            Wfg + (size_t)(F_L[(f + 1 < 54) ? f + 1 : f] * 16) * 32 + lane;

        // tap addresses for this feature (ALU only, hidden)
        const int ii = F_I[f], jj = F_J[f];
        const int di = ii / 3, dj = ii % 3;
        const bool quad = (jj != 255);
        const int dr = quad ? jj / 3 : di, dc = quad ? jj % 3 : dj;
        #pragma unroll
        for (int mi = 0; mi < 8; ++mi) {
            const int wp = mi * 8 + r;
            ib[mi] = sb + ((irow + di) * XS_ROW + (wp + dj) * XS_STRIDE) * 2
                   + t4 * 4;
            jb[mi] = sb + ((irow + dr) * XS_ROW + (wp + dc) * XS_STRIDE) * 2
                   + t4 * 4;
        }

        #pragma unroll
        for (int q = 0; q < 4; ++q) {
            // prefetch NEXT q-step's B fragments (or next feature's q=0)
            const uint4* wsrc = (q < 3) ? (wf + (q + 1) * 4 * 32) : wfn;
            #pragma unroll
            for (int g2 = 0; g2 < 4; ++g2)
                bv[(q + 1) & 1][g2] = __ldg(wsrc + g2 * 32);

            // A fragments for this q (short LDS chain, warp-multiplexed)
            build_ha(ha, ib, jb, q, quad);

            const uint4* bc = bv[q & 1];
            #pragma unroll
            for (int mb = 0; mb < 4; ++mb) {
                #pragma unroll
                for (int g2 = 0; g2 < 4; ++g2) {
                    mma16816(acc[mb][2 * g2],
                             ha[2 * mb][0], ha[2 * mb + 1][0],
                             ha[2 * mb][1], ha[2 * mb + 1][1],
                             bc[g2].x, bc[g2].y);
                    mma16816(acc[mb][2 * g2 + 1],
                             ha[2 * mb][0], ha[2 * mb + 1][0],
                             ha[2 * mb][1], ha[2 * mb + 1][1],
                             bc[g2].z, bc[g2].w);
                }
            }
        }
        wf = wfn;
    }

    // ---- epilogue: exact bias add + float2 stores ----
    const int mrow0 = blockIdx.x * 256 + warp * 64 + r;
    #pragma unroll
    for (int mb = 0; mb < 4; ++mb) {
        #pragma unroll
        for (int nt = 0; nt < 8; ++nt) {
            const int n = nt * 8 + t4 * 2;
            const float bvx = bvecg[n], bvy = bvecg[n + 1];
            float* o0 = out + (size_t)(mrow0 + mb * 16) * 64 + n;
            *(float2*)o0 = make_float2(acc[mb][nt][0] + bvx, acc[mb][nt][1] + bvy);
            *(float2*)(o0 + 8 * 64) =
                make_float2(acc[mb][nt][2] + bvx, acc[mb][nt][3] + bvy);
        }
    }
}

extern "C" void kernel_launch(void* const* d_in, const int* in_sizes, int n_in,
                              void* d_out, int out_size) {
    const float* x  = (const float*)d_in[0];
    const float* wk = (const float*)d_in[1];   // [55,64,64] (l,c,o) contiguous
    float* out = (float*)d_out;

    prep_W<<<55, 512>>>(wk);
    cudaFuncSetAttribute(qconv_mma,
                         cudaFuncAttributeMaxDynamicSharedMemorySize, SMEM_BYTES);
    qconv_mma<<<256, 128, SMEM_BYTES>>>(x, out);
}